// round 17
// baseline (speedup 1.0000x reference)
#include <cuda_runtime.h>
#include <cuda_bf16.h>
#include <cstdint>

// ---------------------------------------------------------------------------
// CTRGC round 17: merged single-barrier pipeline, TT=4 (divides T exactly).
// Per phase j (ONE __syncthreads), all warps run:
//   prefetch LDG(tile i+148, coalesced) | stage B(tile i-148) from YA[(j-1)&1]
//   | stage A(tile i) staging[j&1] -> YA[j&1] | pack staging[(j+1)&1].
// YA and staging double-buffered; W + M' in smem. MMA order per output
// element identical to R8/R16 -> rel_err must be exactly 5.847195e-06.
// ---------------------------------------------------------------------------

#define TFULL 256
#define CIN 64
#define VD 18
#define TT 4
#define NTILES 8192            // 128 n * 64 tiles, all full
#define THREADS 512
#define GRID 148
#define STP 76                 // staging pitch (words): bank=(12c+p)%32 conflict-free

// ---- smem byte offsets ----
#define OFF_M   0                      // M' uint4: 12*32*16 = 6144
#define OFF_ST  6144                   // staging: 2 x 64*76*4 = 2 x 19456
#define STG_BUF 19456
#define OFF_YA  45056                  // YA: 2 x (hi 32768 + lo 32768)
#define YA_BUF  65536
#define YA_HALF 32768
#define OFF_WAH 176128                 // W A-frags hi: 24576
#define OFF_WAL (176128 + 24576)       // W A-frags lo: 24576
#define SMEM_BYTES 225280

// prepped parameters (device globals)
__device__ uint4 d_WfH[12 * 4 * 32];
__device__ uint4 d_WfL[12 * 4 * 32];
__device__ uint4 d_Mf[12 * 32];        // (bh0, bl0, bh1, bl1)
__device__ float d_Cf[64];

__device__ __forceinline__ uint32_t pack2bf(float x, float y) {
    __nv_bfloat162 t = __floats2bfloat162_rn(x, y);   // x -> low half
    return *reinterpret_cast<uint32_t*>(&t);
}

// pack one float into (lo_bf16 << 16) | hi_bf16
__device__ __forceinline__ uint32_t pack_hl(float v) {
    __nv_bfloat16 hb = __float2bfloat16(v);
    float hf = __bfloat162float(hb);
    __nv_bfloat16 lb = __float2bfloat16(v - hf);
    uint16_t hbits = *reinterpret_cast<uint16_t*>(&hb);
    uint16_t lbits = *reinterpret_cast<uint16_t*>(&lb);
    return ((uint32_t)lbits << 16) | hbits;
}

// M'[kc][w]: kc<54 -> M_{kc/18}[kc%18][w]; kc==54 -> 1 (bias lane); else 0.
__device__ float mprime(const float* A, const float* PA, int kc, int w) {
    if (w >= VD) return 0.0f;
    if (kc < 54) {
        int k = kc / 18, v = kc - 18 * k;
        return A[(k * VD + v) * VD + w] + PA[(k * VD + v) * VD + w];
    }
    return (kc == 54) ? 1.0f : 0.0f;
}

__global__ void prep_kernel(const float* __restrict__ A, const float* __restrict__ PA,
                            const float* __restrict__ Wta, const float* __restrict__ bta,
                            const float* __restrict__ g_ta, const float* __restrict__ b_ta,
                            const float* __restrict__ m_ta, const float* __restrict__ v_ta,
                            const float* __restrict__ g_bn, const float* __restrict__ b_bn,
                            const float* __restrict__ m_bn, const float* __restrict__ v_bn)
{
    int tid = threadIdx.x;
    // ---- W A-fragments: rows (k,o) 192 = 12 strips, K = c (64, 4 ks) ----
    for (int idx = tid; idx < 12 * 4 * 32; idx += blockDim.x) {
        int strip = idx >> 7;
        int ks = (idx >> 5) & 3;
        int lane = idx & 31;
        int g = lane >> 2, tig = lane & 3;
        int c0 = ks * 16 + 2 * tig;
        float vals[8];
#pragma unroll
        for (int e = 0; e < 8; e++) {
            int row = strip * 16 + g + ((e >> 1) & 1) * 8;
            int c = c0 + (e & 1) + (e >> 2) * 8;
            int k = row >> 6, o = row & 63;
            float s2 = g_bn[o] * rsqrtf(v_bn[o] + 1e-5f);
            float s1 = g_ta[k * 64 + o] * rsqrtf(v_ta[k * 64 + o] + 1e-5f);
            vals[e] = s2 * s1 * Wta[(k * 64 + o) * 64 + c];
        }
        float hf[8], lf[8];
#pragma unroll
        for (int e = 0; e < 8; e++) {
            __nv_bfloat16 h = __float2bfloat16(vals[e]);
            hf[e] = __bfloat162float(h);
            lf[e] = vals[e] - hf[e];
        }
        d_WfH[idx] = make_uint4(pack2bf(hf[0], hf[1]), pack2bf(hf[2], hf[3]),
                                pack2bf(hf[4], hf[5]), pack2bf(hf[6], hf[7]));
        d_WfL[idx] = make_uint4(pack2bf(lf[0], lf[1]), pack2bf(lf[2], lf[3]),
                                pack2bf(lf[4], lf[5]), pack2bf(lf[6], lf[7]));
    }
    // ---- M' B-fragments: uint4 = (bh0, bl0, bh1, bl1) per (nb,ks,lane) ----
    for (int idx = tid; idx < 12 * 32; idx += blockDim.x) {
        int nb = idx >> 7;
        int ks = (idx >> 5) & 3;
        int lane = idx & 31;
        int g = lane >> 2, tig = lane & 3;
        int wcol = nb * 8 + g;
        int kc0 = ks * 16 + 2 * tig;
        float vals[4] = { mprime(A, PA, kc0, wcol),     mprime(A, PA, kc0 + 1, wcol),
                          mprime(A, PA, kc0 + 8, wcol), mprime(A, PA, kc0 + 9, wcol) };
        float hf[4], lf[4];
#pragma unroll
        for (int e = 0; e < 4; e++) {
            __nv_bfloat16 h = __float2bfloat16(vals[e]);
            hf[e] = __bfloat162float(h);
            lf[e] = vals[e] - hf[e];
        }
        d_Mf[idx] = make_uint4(pack2bf(hf[0], hf[1]), pack2bf(lf[0], lf[1]),
                               pack2bf(hf[2], hf[3]), pack2bf(lf[2], lf[3]));
    }
    // ---- folded bias ----
    if (tid < 64) {
        int o = tid;
        float s2 = g_bn[o] * rsqrtf(v_bn[o] + 1e-5f);
        float acc = 0.0f;
        for (int k = 0; k < 3; k++) {
            float s1 = g_ta[k * 64 + o] * rsqrtf(v_ta[k * 64 + o] + 1e-5f);
            acc += s1 * (bta[k * 64 + o] - m_ta[k * 64 + o]) + b_ta[k * 64 + o];
        }
        d_Cf[o] = s2 * acc + b_bn[o] - m_bn[o] * s2;
    }
}

// ---- HMMA m16n8k16 bf16, f32 accum ----
__device__ __forceinline__ void mma_bf16(float* d, uint32_t a0, uint32_t a1,
                                         uint32_t a2, uint32_t a3,
                                         uint32_t b0, uint32_t b1) {
    asm("mma.sync.aligned.m16n8k16.row.col.f32.bf16.bf16.f32 "
        "{%0,%1,%2,%3},{%4,%5,%6,%7},{%8,%9},{%0,%1,%2,%3};"
        : "+f"(d[0]), "+f"(d[1]), "+f"(d[2]), "+f"(d[3])
        : "r"(a0), "r"(a1), "r"(a2), "r"(a3), "r"(b0), "r"(b1));
}

extern __shared__ char smem[];

// YA word: ((frag*4 + reg) * 32 + lane) ; frag = strip*4 + ks (16 strips)
__device__ __forceinline__ int ya_off(int frag, int reg, int lane) {
    return (((frag * 4 + reg) * 32) + lane) * 4;
}

__device__ __forceinline__ void ya_write(char* baseH, char* baseL,
                                         int row2, int kcol, float d0, float d1) {
    int strip2 = row2 >> 4, r2 = row2 & 15;
    int ks2 = kcol >> 4, cc2 = kcol & 15;
    int lane2 = (r2 & 7) * 4 + ((cc2 >> 1) & 3);
    int reg2 = (r2 >> 3) + 2 * (cc2 >> 3);
    int off = ya_off(strip2 * 4 + ks2, reg2, lane2);
    __nv_bfloat16 h0 = __float2bfloat16(d0);
    __nv_bfloat16 h1 = __float2bfloat16(d1);
    float h0f = __bfloat162float(h0), h1f = __bfloat162float(h1);
    *reinterpret_cast<uint32_t*>(baseH + off) = pack2bf(h0f, h1f);
    *reinterpret_cast<uint32_t*>(baseL + off) = pack2bf(d0 - h0f, d1 - h1f);
}

__global__ __launch_bounds__(THREADS, 1)
void ctrgc17(const float* __restrict__ x, float* __restrict__ out)
{
    const int tid = threadIdx.x;
    const int w = tid >> 5;      // warp 0..15
    const int lane = tid & 31;
    const int g = lane >> 2;
    const int tig = lane & 3;

    uint32_t* stgW0 = reinterpret_cast<uint32_t*>(smem + OFF_ST);

    // ---- one-time init: W frags, M' frags, zero both YA buffers ----
    {
        uint4* wh = reinterpret_cast<uint4*>(smem + OFF_WAH);
        uint4* wl = reinterpret_cast<uint4*>(smem + OFF_WAL);
        for (int i = tid; i < 12 * 4 * 32; i += THREADS) { wh[i] = d_WfH[i]; wl[i] = d_WfL[i]; }
        uint4* mf = reinterpret_cast<uint4*>(smem + OFF_M);
        for (int i = tid; i < 12 * 32; i += THREADS) mf[i] = d_Mf[i];
        uint32_t* ya = reinterpret_cast<uint32_t*>(smem + OFF_YA);
        for (int i = tid; i < 2 * YA_BUF / 4; i += THREADS) ya[i] = 0u;
    }
    __syncthreads();
    // bias column kcol=54 into both YA buffers (rows 0..255)
    if (tid < 256) {
        float cf = d_Cf[tid & 63];
        ya_write(smem + OFF_YA, smem + OFF_YA + YA_HALF, tid, 54, cf, 0.0f);
        ya_write(smem + OFF_YA + YA_BUF, smem + OFF_YA + YA_BUF + YA_HALF, tid, 54, cf, 0.0f);
    }
    // prologue: pack tile(blockIdx.x) into staging buf 0 (coalesced LDG+STS)
    {
        int tile = blockIdx.x;
        int n = tile >> 6;
        int t0 = (tile & 63) * TT;
        const float* xs = x + (size_t)n * (CIN * TFULL * VD) + (size_t)t0 * VD;
#pragma unroll
        for (int m = 0; m < 9; m++) {
            int idx = tid + m * THREADS;     // 0..4607
            int c = idx / 72, p = idx - 72 * c;
            stgW0[c * STP + p] = pack_hl(__ldg(xs + c * (TFULL * VD) + p));
        }
    }
    __syncthreads();

    // SMSP-balanced role constants: sg = w&3 (same strips per SMSP, W reuse),
    // pg = w>>2 (each SMSP holds one pg of each value -> balanced MMA load)
    const int sg = w & 3;     // strips {sg, sg+4, sg+8}
    const int pg = w >> 2;    // posblks {pg, pg+4, pg+8} intersect [0,8]
    const int npb = (pg == 0) ? 3 : 2;

    for (int j = 0;; j++) {
        const int iA = blockIdx.x + j * GRID;
        const int iB = iA - GRID;
        const bool hasA = (iA < NTILES);
        const bool hasB = (j > 0) && (iB < NTILES);
        if (!hasA && !hasB) break;

        uint32_t* stgR = reinterpret_cast<uint32_t*>(smem + OFF_ST + (j & 1) * STG_BUF);
        uint32_t* stgW = reinterpret_cast<uint32_t*>(smem + OFF_ST + ((j + 1) & 1) * STG_BUF);
        char* yaWH = smem + OFF_YA + (j & 1) * YA_BUF;
        char* yaWL = yaWH + YA_HALF;
        char* yaRH = smem + OFF_YA + ((j + 1) & 1) * YA_BUF;   // == (j-1)&1
        char* yaRL = yaRH + YA_HALF;

        // ---- 1. prefetch LDG for tile iA+GRID (consumed as staging next phase)
        const bool hasN = hasA && (iA + GRID < NTILES);
        float pf[9];
        if (hasN) {
            int tn = iA + GRID;
            int nn = tn >> 6;
            int tn0 = (tn & 63) * TT;
            const float* xs = x + (size_t)nn * (CIN * TFULL * VD) + (size_t)tn0 * VD;
#pragma unroll
            for (int m = 0; m < 9; m++) {
                int idx = tid + m * THREADS;
                int c = idx / 72, p = idx - 72 * c;
                pf[m] = __ldg(xs + c * (TFULL * VD) + p);
            }
        }

        // ---- 2. stage B(iB): YA[(j-1)&1] x M' -> out ----
        if (hasB) {
            const int nB = iB >> 6;
            const int t0B = (iB & 63) * TT;
            uint4 mf[3][4];
#pragma unroll
            for (int nb = 0; nb < 3; nb++)
#pragma unroll
                for (int ks = 0; ks < 4; ks++)
                    mf[nb][ks] = *reinterpret_cast<const uint4*>(
                        smem + OFF_M + (((nb * 4 + ks) * 32 + lane) << 4));
            uint4 ah[4], al[4];
#pragma unroll
            for (int ks = 0; ks < 4; ks++) {
                int f = w * 4 + ks;          // strip = w (0..15)
                ah[ks].x = *reinterpret_cast<const uint32_t*>(yaRH + ya_off(f, 0, lane));
                ah[ks].y = *reinterpret_cast<const uint32_t*>(yaRH + ya_off(f, 1, lane));
                ah[ks].z = *reinterpret_cast<const uint32_t*>(yaRH + ya_off(f, 2, lane));
                ah[ks].w = *reinterpret_cast<const uint32_t*>(yaRH + ya_off(f, 3, lane));
                al[ks].x = *reinterpret_cast<const uint32_t*>(yaRL + ya_off(f, 0, lane));
                al[ks].y = *reinterpret_cast<const uint32_t*>(yaRL + ya_off(f, 1, lane));
                al[ks].z = *reinterpret_cast<const uint32_t*>(yaRL + ya_off(f, 2, lane));
                al[ks].w = *reinterpret_cast<const uint32_t*>(yaRL + ya_off(f, 3, lane));
            }
            const int rowB = w * 16 + g;
            const int tB = rowB >> 6;        // 0..3, always valid (TT=4 exact)
            const int oB = rowB & 63;
#pragma unroll
            for (int nb = 0; nb < 3; nb++) {
                float D2[4] = {0.0f, 0.0f, 0.0f, 0.0f};
#pragma unroll
                for (int ks = 0; ks < 4; ks++) {
                    mma_bf16(D2, ah[ks].x, ah[ks].y, ah[ks].z, ah[ks].w,
                             mf[nb][ks].x, mf[nb][ks].z);
                    mma_bf16(D2, ah[ks].x, ah[ks].y, ah[ks].z, ah[ks].w,
                             mf[nb][ks].y, mf[nb][ks].w);
                    mma_bf16(D2, al[ks].x, al[ks].y, al[ks].z, al[ks].w,
                             mf[nb][ks].x, mf[nb][ks].z);
                }
                int w0 = nb * 8 + 2 * tig;
                if (w0 < VD) {
                    size_t base = ((size_t)(nB * 64 + oB) * TFULL + (t0B + tB)) * VD + w0;
                    *reinterpret_cast<float2*>(out + base) =
                        make_float2(fmaxf(D2[0], 0.0f), fmaxf(D2[1], 0.0f));
                    size_t base2 = base + (size_t)8 * TFULL * VD;   // o+8
                    *reinterpret_cast<float2*>(out + base2) =
                        make_float2(fmaxf(D2[2], 0.0f), fmaxf(D2[3], 0.0f));
                }
            }
        }

        // ---- 3. stage A(iA): staging[j&1] (PRMT) x W -> YA[j&1] ----
        if (hasA) {
            uint2 xbh[3][4], xbl[3][4];
#pragma unroll
            for (int p_i = 0; p_i < 3; p_i++) {
                if (p_i < npb) {
                    const int pos = (pg + 4 * p_i) * 8 + g;
#pragma unroll
                    for (int ks = 0; ks < 4; ks++) {
                        const int c0 = ks * 16 + 2 * tig;
                        uint32_t q00 = stgR[c0 * STP + pos];
                        uint32_t q01 = stgR[(c0 + 1) * STP + pos];
                        uint32_t q10 = stgR[(c0 + 8) * STP + pos];
                        uint32_t q11 = stgR[(c0 + 9) * STP + pos];
                        xbh[p_i][ks].x = __byte_perm(q00, q01, 0x5410);
                        xbl[p_i][ks].x = __byte_perm(q00, q01, 0x7632);
                        xbh[p_i][ks].y = __byte_perm(q10, q11, 0x5410);
                        xbl[p_i][ks].y = __byte_perm(q10, q11, 0x7632);
                    }
                }
            }
#pragma unroll
            for (int s_i = 0; s_i < 3; s_i++) {
                const int s = sg + 4 * s_i;
                uint4 ah[4], al[4];
#pragma unroll
                for (int ks = 0; ks < 4; ks++) {
                    ah[ks] = *reinterpret_cast<const uint4*>(
                        smem + OFF_WAH + (((s * 4 + ks) * 32 + lane) << 4));
                    al[ks] = *reinterpret_cast<const uint4*>(
                        smem + OFF_WAL + (((s * 4 + ks) * 32 + lane) << 4));
                }
                const int rowA0 = s * 16 + g;
                const int k0 = rowA0 >> 6, o0 = rowA0 & 63;
                const int rowA1 = rowA0 + 8;
                const int k1 = rowA1 >> 6, o1 = rowA1 & 63;
#pragma unroll
                for (int p_i = 0; p_i < 3; p_i++) {
                    if (p_i < npb) {
                        const int p0 = (pg + 4 * p_i) * 8 + 2 * tig;   // <= 70
                        float D[4] = {0.0f, 0.0f, 0.0f, 0.0f};
#pragma unroll
                        for (int ks = 0; ks < 4; ks++) {
                            mma_bf16(D, ah[ks].x, ah[ks].y, ah[ks].z, ah[ks].w,
                                     xbh[p_i][ks].x, xbh[p_i][ks].y);
                            mma_bf16(D, ah[ks].x, ah[ks].y, ah[ks].z, ah[ks].w,
                                     xbl[p_i][ks].x, xbl[p_i][ks].y);
                            mma_bf16(D, al[ks].x, al[ks].y, al[ks].z, al[ks].w,
                                     xbh[p_i][ks].x, xbh[p_i][ks].y);
                        }
                        int tloc = (p0 * 228) >> 12;
                        int vloc = p0 - 18 * tloc;
                        ya_write(yaWH, yaWL, tloc * 64 + o0, k0 * 18 + vloc, D[0], D[1]);
                        ya_write(yaWH, yaWL, tloc * 64 + o1, k1 * 18 + vloc, D[2], D[3]);
                    }
                }
            }
        }

        // ---- 4. pack prefetched tile into staging[(j+1)&1] ----
        if (hasN) {
#pragma unroll
            for (int m = 0; m < 9; m++) {
                int idx = tid + m * THREADS;
                int c = idx / 72, p = idx - 72 * c;
                stgW[c * STP + p] = pack_hl(pf[m]);
            }
        }

        __syncthreads();
    }
}

extern "C" void kernel_launch(void* const* d_in, const int* in_sizes, int n_in,
                              void* d_out, int out_size)
{
    (void)in_sizes; (void)n_in; (void)out_size;
    const float* x    = (const float*)d_in[0];
    const float* A    = (const float*)d_in[1];
    const float* PA   = (const float*)d_in[2];
    const float* Wta  = (const float*)d_in[3];
    const float* bta  = (const float*)d_in[4];
    const float* g_ta = (const float*)d_in[5];
    const float* b_ta = (const float*)d_in[6];
    const float* m_ta = (const float*)d_in[7];
    const float* v_ta = (const float*)d_in[8];
    // d_in[9..12] dead attention branch
    const float* g_bn = (const float*)d_in[13];
    const float* b_bn = (const float*)d_in[14];
    const float* m_bn = (const float*)d_in[15];
    const float* v_bn = (const float*)d_in[16];
    float* out = (float*)d_out;

    cudaFuncSetAttribute(ctrgc17, cudaFuncAttributeMaxDynamicSharedMemorySize, SMEM_BYTES);

    prep_kernel<<<1, 256>>>(A, PA, Wta, bta, g_ta, b_ta, m_ta, v_ta,
                            g_bn, b_bn, m_bn, v_bn);
    ctrgc17<<<GRID, THREADS, SMEM_BYTES>>>(x, out);
}